// round 10
// baseline (speedup 1.0000x reference)
#include <cuda_runtime.h>

// QuantizedLinear(5 -> 10, bits=2) over 4M tokens, fp32.
//
// v1's high-occupancy one-tile-per-block structure, but the 2-bit-dequantized
// weights live in REGISTERS via a thread-pair output split (even lane:
// outputs 0-4, odd lane: 5-9; each pair shares one token). This removes the
// 60 broadcast weight-LDS per token that bound v1 at L1=82%. All global
// traffic stays coalesced float4 via smem staging.

#define THREADS 256
#define TPB 128                 // tokens per block (one thread PAIR per token)
#define IN_F 5
#define OUT_F 10
#define XF (TPB * IN_F)         // 640 floats
#define OF (TPB * OUT_F)        // 1280 floats

__global__ __launch_bounds__(THREADS)
void qlinear2bit_kernel(const float* __restrict__ x,
                        const float* __restrict__ w,
                        const float* __restrict__ bias,
                        float* __restrict__ out,
                        int n_tokens)
{
    __shared__ float sx[XF];    // 2.5 KB
    __shared__ float so[OF];    // 5 KB

    const int t = threadIdx.x;
    const int p = t >> 1;       // token within tile (0..127)
    const int h = t & 1;        // output half: rows h*5 .. h*5+4

    const long long tok0 = (long long)blockIdx.x * TPB;

    // ---- coalesced load of x tile (issue LDG before weight dequant) ----
    const long long xbase = tok0 * IN_F;
    const long long xtotal = (long long)n_tokens * IN_F;
    const bool full = (tok0 + TPB <= (long long)n_tokens);
    if (full) {
        if (t < XF / 4)                                  // 160 float4
            ((float4*)sx)[t] = ((const float4*)(x + xbase))[t];
    } else {
        const int nf = (int)(xtotal - xbase);
        for (int i = t; i < nf; i += THREADS)
            sx[i] = x[xbase + i];
    }

    // ---- dequantize this thread's 5 weight rows into registers ----
    float wd[5][IN_F], b[5];
    #pragma unroll
    for (int j = 0; j < 5; j++) {
        const int o = h * 5 + j;
        float m = 0.0f;
        #pragma unroll
        for (int c = 0; c < IN_F; c++) {
            wd[j][c] = __ldg(&w[o * IN_F + c]);
            m = fmaxf(m, fabsf(wd[j][c]));
        }
        float scale = fmaxf(m, 1e-8f);          // qmax = 2^(bits-1)-1 = 1
        float inv = 1.0f / scale;
        #pragma unroll
        for (int c = 0; c < IN_F; c++) {
            float q = rintf(wd[j][c] * inv);    // round-half-to-even == jnp.round
            wd[j][c] = fminf(fmaxf(q, -2.0f), 1.0f) * scale;
        }
        b[j] = __ldg(&bias[o]);
    }
    __syncthreads();

    // ---- compute: pair shares token p; weights from registers ----
    if (tok0 + p < (long long)n_tokens) {
        float xi[IN_F];
        #pragma unroll
        for (int c = 0; c < IN_F; c++)
            xi[c] = sx[p * IN_F + c];            // pair-broadcast, conflict-free
        #pragma unroll
        for (int j = 0; j < 5; j++) {
            float acc = b[j];
            #pragma unroll
            for (int c = 0; c < IN_F; c++)
                acc = fmaf(xi[c], wd[j][c], acc);
            so[p * OUT_F + h * 5 + j] = acc;     // banks 10p+5h+j: conflict-free
        }
    }
    __syncthreads();

    // ---- coalesced store of out tile ----
    const long long obase = tok0 * OUT_F;
    if (full) {
        float4* og = (float4*)(out + obase);     // 320 float4
        const float4* ss = (const float4*)so;
        og[t] = ss[t];
        if (t < OF / 4 - THREADS)
            og[THREADS + t] = ss[THREADS + t];
    } else {
        const int nof = (int)((long long)n_tokens * OUT_F - obase);
        for (int i = t; i < nof; i += THREADS)
            out[obase + i] = so[i];
    }
}

extern "C" void kernel_launch(void* const* d_in, const int* in_sizes, int n_in,
                              void* d_out, int out_size)
{
    const float* x    = (const float*)d_in[0];   // [N, 5]
    const float* w    = (const float*)d_in[1];   // [10, 5]
    const float* bias = (const float*)d_in[2];   // [10]
    float* out = (float*)d_out;                  // [N, 10]

    const int n_tokens = in_sizes[0] / IN_F;
    const int grid = (n_tokens + TPB - 1) / TPB;
    qlinear2bit_kernel<<<grid, THREADS>>>(x, w, bias, out, n_tokens);
}

// round 11
// speedup vs baseline: 1.4739x; 1.4739x over previous
#include <cuda_runtime.h>

// QuantizedLinear(5 -> 10, bits=2) over 4M tokens, fp32.
//
// Two launches:
//  1) dequant_kernel: dequantizes the 10x5 2-bit weight + bias ONCE into a
//     __device__ array, packed per output-half (25 w + 5 bias, float4-aligned).
//  2) main kernel: v1's high-occupancy one-tile-per-block structure.
//     Thread-pair output split (even lane: outputs 0-4, odd: 5-9); each pair
//     handles tokens p and p+128. Weights live in registers via 8 broadcast
//     LDG.128 (L1-hot). All global x/out traffic coalesced float4 via smem.

#define THREADS 256
#define TPB 256                 // tokens per block
#define IN_F 5
#define OUT_F 10
#define XF (TPB * IN_F)         // 1280 floats
#define OF (TPB * OUT_F)        // 2560 floats

// [h][32]: elements 0..24 = w_deq rows h*5..h*5+4 (row-major), 25..29 = bias
__device__ float g_wb[64];

__global__ void dequant_kernel(const float* __restrict__ w,
                               const float* __restrict__ bias)
{
    const int o = threadIdx.x;          // 0..9
    if (o < OUT_F) {
        float r[IN_F];
        float m = 0.0f;
        #pragma unroll
        for (int c = 0; c < IN_F; c++) {
            r[c] = w[o * IN_F + c];
            m = fmaxf(m, fabsf(r[c]));
        }
        float scale = fmaxf(m, 1e-8f);          // qmax = 2^(bits-1)-1 = 1
        float inv = 1.0f / scale;
        const int h = o / 5, j = o % 5;
        #pragma unroll
        for (int c = 0; c < IN_F; c++) {
            float q = rintf(r[c] * inv);        // round-half-to-even == jnp.round
            g_wb[h * 32 + j * IN_F + c] = fminf(fmaxf(q, -2.0f), 1.0f) * scale;
        }
        g_wb[h * 32 + 25 + j] = bias[o];
    } else if (o >= OUT_F && o < 64) {
        // zero the pad so LDG.128 reads defined memory
        if (o == 10 || o == 11) {
            g_wb[30 + (o - 10)] = 0.0f;
            g_wb[62 + (o - 10)] = 0.0f;
        }
    }
}

__global__ __launch_bounds__(THREADS)
void qlinear2bit_kernel(const float* __restrict__ x,
                        float* __restrict__ out,
                        int n_tokens)
{
    __shared__ float sx[XF];    // 5 KB
    __shared__ float so[OF];    // 10 KB

    const int t = threadIdx.x;
    const int p = t >> 1;       // pair index (0..127)
    const int h = t & 1;        // output half: rows h*5 .. h*5+4

    const long long tok0 = (long long)blockIdx.x * TPB;
    const bool full = (tok0 + TPB <= (long long)n_tokens);

    // ---- coalesced load of x tile (issue LDG first) ----
    const long long xbase = tok0 * IN_F;
    if (full) {
        const float4* xg = (const float4*)(x + xbase);  // 320 float4
        float4* ss = (float4*)sx;
        ss[t] = xg[t];
        if (t < XF / 4 - THREADS) ss[THREADS + t] = xg[THREADS + t];
    } else {
        const int nf = (int)((long long)n_tokens * IN_F - xbase);
        for (int i = t; i < nf; i += THREADS)
            sx[i] = x[xbase + i];
    }

    // ---- weights + bias into registers: 8 broadcast LDG.128 (L1-hot) ----
    float wr[32];
    {
        const float4* wb4 = (const float4*)g_wb;
        #pragma unroll
        for (int i = 0; i < 8; i++)
            ((float4*)wr)[i] = wb4[h * 8 + i];
    }
    __syncthreads();

    // ---- compute: pair shares tokens p and p+128; weights in registers ----
    #pragma unroll
    for (int s = 0; s < 2; s++) {
        const int tok = p + s * 128;
        if (tok0 + tok < (long long)n_tokens) {
            float xi[IN_F];
            #pragma unroll
            for (int c = 0; c < IN_F; c++)
                xi[c] = sx[tok * IN_F + c];          // pair-broadcast, no conflicts
            #pragma unroll
            for (int j = 0; j < 5; j++) {
                float acc = wr[25 + j];              // bias
                #pragma unroll
                for (int c = 0; c < IN_F; c++)
                    acc = fmaf(xi[c], wr[j * IN_F + c], acc);
                so[tok * OUT_F + h * 5 + j] = acc;   // banks 10tok+5h+j: conflict-free
            }
        }
    }
    __syncthreads();

    // ---- coalesced store of out tile ----
    const long long obase = tok0 * OUT_F;
    if (full) {
        float4* og = (float4*)(out + obase);         // 640 float4
        const float4* ss = (const float4*)so;
        og[t] = ss[t];
        og[THREADS + t] = ss[THREADS + t];
        if (t < OF / 4 - 2 * THREADS)
            og[2 * THREADS + t] = ss[2 * THREADS + t];
    } else {
        const int nof = (int)((long long)n_tokens * OUT_F - obase);
        for (int i = t; i < nof; i += THREADS)
            out[obase + i] = so[i];
    }
}

extern "C" void kernel_launch(void* const* d_in, const int* in_sizes, int n_in,
                              void* d_out, int out_size)
{
    const float* x    = (const float*)d_in[0];   // [N, 5]
    const float* w    = (const float*)d_in[1];   // [10, 5]
    const float* bias = (const float*)d_in[2];   // [10]
    float* out = (float*)d_out;                  // [N, 10]

    const int n_tokens = in_sizes[0] / IN_F;
    dequant_kernel<<<1, 64>>>(w, bias);
    const int grid = (n_tokens + TPB - 1) / TPB;
    qlinear2bit_kernel<<<grid, THREADS>>>(x, out, n_tokens);
}

// round 12
// speedup vs baseline: 2.4431x; 1.6576x over previous
#include <cuda_runtime.h>
#include <cstdint>

// QuantizedLinear(5 -> 10, bits=2) over 4M tokens, fp32.
//
// TMA (1D cp.async.bulk) moves the contiguous x/out tiles gmem<->smem without
// touching the SM's L1/LSU wavefront budget (the proven bottleneck of every
// smem-staged variant). Compute uses a 5-way lane split: thread j=t%5 owns
// output rows {2j, 2j+1} (12 weight registers, dequantized in-block by
// threads 0..9 while the TMA load is in flight). 512 tokens/block, 320
// threads, 6 blocks/SM.

#define THREADS 320
#define TPB 512                  // tokens per block
#define IN_F 5
#define OUT_F 10
#define ROUNDS (TPB / 64)        // 64 tokens per round (320 threads / 5)
#define XBYTES (TPB * IN_F * 4)  // 10240
#define OBYTES (TPB * OUT_F * 4) // 20480

__global__ __launch_bounds__(THREADS)
void qlinear2bit_kernel(const float* __restrict__ x,
                        const float* __restrict__ w,
                        const float* __restrict__ bias,
                        float* __restrict__ out,
                        int n_tokens)
{
    __shared__ __align__(128) float sx[TPB * IN_F];    // 10 KB
    __shared__ __align__(128) float so[TPB * OUT_F];   // 20 KB
    __shared__ float sw[OUT_F * IN_F];
    __shared__ float sb[OUT_F];
    __shared__ __align__(8) unsigned long long mbar;

    const int t = threadIdx.x;
    const long long tok0 = (long long)blockIdx.x * TPB;
    const bool full = (tok0 + TPB <= (long long)n_tokens);

    const uint32_t smem_x = (uint32_t)__cvta_generic_to_shared(sx);
    const uint32_t smem_o = (uint32_t)__cvta_generic_to_shared(so);
    const uint32_t mb     = (uint32_t)__cvta_generic_to_shared(&mbar);

    // ---- kick off TMA load of the x tile (full blocks) ----
    if (full && t == 0) {
        asm volatile("mbarrier.init.shared.b64 [%0], 1;" :: "r"(mb));
        asm volatile("fence.proxy.async.shared::cta;" ::: "memory");
        asm volatile("mbarrier.arrive.expect_tx.shared.b64 _, [%0], %1;"
                     :: "r"(mb), "r"((uint32_t)XBYTES));
        asm volatile(
            "cp.async.bulk.shared::cluster.global.mbarrier::complete_tx::bytes "
            "[%0], [%1], %2, [%3];"
            :: "r"(smem_x), "l"(x + tok0 * IN_F), "r"((uint32_t)XBYTES), "r"(mb)
            : "memory");
    }

    // ---- dequantize weights into smem (threads 0..9), overlapped w/ TMA ----
    if (t < OUT_F) {
        float r[IN_F];
        float m = 0.0f;
        #pragma unroll
        for (int c = 0; c < IN_F; c++) {
            r[c] = w[t * IN_F + c];
            m = fmaxf(m, fabsf(r[c]));
        }
        float scale = fmaxf(m, 1e-8f);          // qmax = 2^(bits-1)-1 = 1
        float inv = 1.0f / scale;
        #pragma unroll
        for (int c = 0; c < IN_F; c++) {
            float q = rintf(r[c] * inv);        // round-half-to-even == jnp.round
            sw[t * IN_F + c] = fminf(fmaxf(q, -2.0f), 1.0f) * scale;
        }
        sb[t] = bias[t];
    }

    // ---- partial (tail) block: scalar x load ----
    if (!full) {
        long long nf = (long long)n_tokens * IN_F - tok0 * IN_F;
        if (nf < 0) nf = 0;
        for (int i = t; i < (int)nf; i += THREADS)
            sx[i] = x[tok0 * IN_F + i];
    }
    __syncthreads();   // sw/sb ready; mbarrier init visible to all

    // ---- wait for TMA x tile ----
    if (full) {
        uint32_t done;
        asm volatile(
            "{\n\t.reg .pred p;\n\t"
            "mbarrier.try_wait.parity.acquire.cta.shared::cta.b64 p, [%1], %2;\n\t"
            "selp.b32 %0, 1, 0, p;\n\t}"
            : "=r"(done) : "r"(mb), "r"(0u) : "memory");
        if (!done) {
            asm volatile(
                "{\n\t.reg .pred P1;\n\t"
                "W_%=:\n\t"
                "mbarrier.try_wait.parity.acquire.cta.shared::cta.b64 P1, [%0], %1, 0x989680;\n\t"
                "@P1 bra.uni D_%=;\n\t"
                "bra.uni W_%=;\n\t"
                "D_%=:\n\t}"
                :: "r"(mb), "r"(0u) : "memory");
        }
    }

    // ---- per-thread weights: rows 2j, 2j+1 (12 registers) ----
    const int p = t / 5;        // token slot within a round (0..63)
    const int j = t % 5;        // output pair selector
    float wd[2][IN_F], b2[2];
    #pragma unroll
    for (int r = 0; r < 2; r++) {
        const int o = 2 * j + r;
        #pragma unroll
        for (int c = 0; c < IN_F; c++) wd[r][c] = sw[o * IN_F + c];
        b2[r] = sb[o];
    }

    // ---- compute: each round covers 64 tokens; thread handles 2 outputs ----
    if (full) {
        #pragma unroll
        for (int s = 0; s < ROUNDS; s++) {
            const int tok = p + 64 * s;
            float xi[IN_F];
            #pragma unroll
            for (int c = 0; c < IN_F; c++)
                xi[c] = sx[tok * IN_F + c];          // 5-lane multicast LDS
            #pragma unroll
            for (int r = 0; r < 2; r++) {
                float acc = b2[r];
                #pragma unroll
                for (int c = 0; c < IN_F; c++)
                    acc = fmaf(xi[c], wd[r][c], acc);
                so[tok * OUT_F + 2 * j + r] = acc;
            }
        }
    } else {
        for (int s = 0; s < ROUNDS; s++) {
            const int tok = p + 64 * s;
            if (tok0 + tok < (long long)n_tokens) {
                float xi[IN_F];
                #pragma unroll
                for (int c = 0; c < IN_F; c++)
                    xi[c] = sx[tok * IN_F + c];
                #pragma unroll
                for (int r = 0; r < 2; r++) {
                    float acc = b2[r];
                    #pragma unroll
                    for (int c = 0; c < IN_F; c++)
                        acc = fmaf(xi[c], wd[r][c], acc);
                    so[tok * OUT_F + 2 * j + r] = acc;
                }
            }
        }
    }
    __syncthreads();   // all so STS complete

    // ---- TMA store of the out tile ----
    if (full) {
        if (t == 0) {
            asm volatile("fence.proxy.async.shared::cta;" ::: "memory");
            asm volatile(
                "cp.async.bulk.global.shared::cta.bulk_group [%0], [%1], %2;"
                :: "l"(out + tok0 * OUT_F), "r"(smem_o), "r"((uint32_t)OBYTES)
                : "memory");
            asm volatile("cp.async.bulk.commit_group;" ::: "memory");
            asm volatile("cp.async.bulk.wait_group 0;" ::: "memory");
        }
        __syncthreads();   // smem must stay alive until the bulk store read it
    } else {
        long long nof = (long long)n_tokens * OUT_F - tok0 * OUT_F;
        if (nof < 0) nof = 0;
        for (int i = t; i < (int)nof; i += THREADS)
            out[tok0 * OUT_F + i] = so[i];
    }
}

extern "C" void kernel_launch(void* const* d_in, const int* in_sizes, int n_in,
                              void* d_out, int out_size)
{
    const float* x    = (const float*)d_in[0];   // [N, 5]
    const float* w    = (const float*)d_in[1];   // [10, 5]
    const float* bias = (const float*)d_in[2];   // [10]
    float* out = (float*)d_out;                  // [N, 10]

    const int n_tokens = in_sizes[0] / IN_F;
    const int grid = (n_tokens + TPB - 1) / TPB;
    qlinear2bit_kernel<<<grid, THREADS>>>(x, w, bias, out, n_tokens);
}